// round 14
// baseline (speedup 1.0000x reference)
#include <cuda_runtime.h>
#include <cuda_bf16.h>
#include <cstdint>

#define NUM_USER  8192
#define NUM_ITEM  16384
#define NUM_HIDDEN 64
#define NNZ       200000

#define BM 128
#define BN 128
#define KPAD 68   // smem row stride in words: all ldmatrix phases conflict-free

__device__ unsigned char g_user_mask[NUM_USER];
__device__ unsigned char g_item_mask[NUM_ITEM];
__device__ int g_idx_is64;

// ---------------------------------------------------------------------------
// tf32 / mma / ldmatrix helpers
// ---------------------------------------------------------------------------
__device__ __forceinline__ uint32_t tf32_of(float x) {
    uint32_t r; asm("cvt.rna.tf32.f32 %0, %1;" : "=r"(r) : "f"(x)); return r;
}

__device__ __forceinline__ void mma_tf32(float* c, const uint32_t* a, const uint32_t* b) {
    asm("mma.sync.aligned.m16n8k8.row.col.f32.tf32.tf32.f32 "
        "{%0,%1,%2,%3}, {%4,%5,%6,%7}, {%8,%9}, {%0,%1,%2,%3};"
        : "+f"(c[0]), "+f"(c[1]), "+f"(c[2]), "+f"(c[3])
        : "r"(a[0]), "r"(a[1]), "r"(a[2]), "r"(a[3]), "r"(b[0]), "r"(b[1]));
}

__device__ __forceinline__ void ldsm_x4(uint32_t* r, uint32_t saddr) {
    asm volatile("ldmatrix.sync.aligned.m8n8.x4.shared.b16 {%0,%1,%2,%3}, [%4];"
        : "=r"(r[0]), "=r"(r[1]), "=r"(r[2]), "=r"(r[3]) : "r"(saddr));
}

__device__ __forceinline__ void ldsm_x2(uint32_t* r, uint32_t saddr) {
    asm volatile("ldmatrix.sync.aligned.m8n8.x2.shared.b16 {%0,%1}, [%2];"
        : "=r"(r[0]), "=r"(r[1]) : "r"(saddr));
}

// ---------------------------------------------------------------------------
// Kernel 0: globally-sequential zero fill of the label half (best measured
// DRAM write rate: grid-stride sweep, contiguous chip-wide bands).
// ---------------------------------------------------------------------------
__global__ void fill_label(float* __restrict__ out) {
    const size_t n4 = (size_t)NUM_USER * NUM_ITEM / 4;
    float4* p = (float4*)(out + (size_t)NUM_USER * NUM_ITEM);
    const float4 z = make_float4(0.f, 0.f, 0.f, 0.f);
    size_t stride = (size_t)gridDim.x * blockDim.x;
    for (size_t k = (size_t)blockIdx.x * blockDim.x + threadIdx.x; k < n4; k += stride)
        __stcs(p + k, z);
}

// ---------------------------------------------------------------------------
// Kernel 1: clear masks, detect index dtype (int32 vs int64), write ratio.
// Values are in [0, 8192): an int64 buffer viewed as int32 has every odd
// word == 0 over 64 samples -> deterministic dtype detection.
// ---------------------------------------------------------------------------
__global__ void clear_masks(const int* __restrict__ idx32, float* __restrict__ out) {
    int t = blockIdx.x * blockDim.x + threadIdx.x;
    if (t == 0) {
        int all0 = 1;
#pragma unroll
        for (int k = 0; k < 64; ++k) all0 &= (idx32[2 * k + 1] == 0);
        g_idx_is64 = all0;
        out[(size_t)2 * NUM_USER * NUM_ITEM] =
            (float)((double)NUM_USER * (double)NUM_ITEM / (double)NNZ);
    }
    int* um = (int*)g_user_mask;
    int* im = (int*)g_item_mask;
    if (t < NUM_USER / 4) um[t] = 0;
    if (t < NUM_ITEM / 4) im[t] = 0;
}

__device__ __forceinline__ void load_pair(const void* idxv, int t, int& u, int& i) {
    if (g_idx_is64) {
        const long long* p = (const long long*)idxv;
        u = (int)__ldg(p + t);
        i = (int)__ldg(p + NNZ + t);
    } else {
        const int* p = (const int*)idxv;
        u = __ldg(p + t);
        i = __ldg(p + NNZ + t);
    }
}

__global__ void set_masks(const void* __restrict__ idxv) {
    int t = blockIdx.x * blockDim.x + threadIdx.x;
    if (t >= NNZ) return;
    int u, i;
    load_pair(idxv, t, u, i);
    g_user_mask[u] = 1;
    g_item_mask[i] = 1;
}

// ---------------------------------------------------------------------------
// Zero a 128x128 tile: contiguous 512B warp bursts, streaming stores.
// ---------------------------------------------------------------------------
__device__ __forceinline__ void zero_tile(float* base, int t) {
    const float4 z = make_float4(0.f, 0.f, 0.f, 0.f);
    const int warp = t >> 5, lane = t & 31;
#pragma unroll
    for (int r = warp; r < BM; r += 8)
        __stcs((float4*)(base + (size_t)r * NUM_ITEM) + lane, z);
}

// ---------------------------------------------------------------------------
// Kernel 3: masked tf32-MMA GEMM, pred only (label handled by fill_label).
// 128x128 tile, 8 warps (2x4), warp tile 64x32, m16n8k8 atoms, ldmatrix.
// ---------------------------------------------------------------------------
__global__ void __launch_bounds__(256, 2)
mf_gemm(const float* __restrict__ eu, const float* __restrict__ ei,
        float* __restrict__ out) {
    __shared__ uint32_t As[BM * KPAD];
    __shared__ uint32_t Bs[BN * KPAD];

    const int t    = threadIdx.x;
    const int row0 = blockIdx.y * BM;
    const int col0 = blockIdx.x * BN;

    int has_item = __syncthreads_or(t < BN ? (int)g_item_mask[col0 + t] : 0);
    int has_user = __syncthreads_or(t < BM ? (int)g_user_mask[row0 + t] : 0);

    float* pred = out + (size_t)row0 * NUM_ITEM + col0;

    if (!has_item || !has_user) {
        zero_tile(pred, t);
        return;
    }

    // Stage A and B (masked, tf32-converted) into smem.
    {
        const int rsub = t >> 2;   // 0..63
        const int f4   = t & 3;
#pragma unroll
        for (int pass = 0; pass < 2; ++pass) {
            const int m = rsub + 64 * pass;
            const float4* arow = (const float4*)(eu + (size_t)(row0 + m) * NUM_HIDDEN);
            const float4* brow = (const float4*)(ei + (size_t)(col0 + m) * NUM_HIDDEN);
            const float um = (float)g_user_mask[row0 + m];
            const float im = (float)g_item_mask[col0 + m];
#pragma unroll
            for (int q = 0; q < 4; ++q) {
                const int kf = f4 + 4 * q;          // float4 slot 0..15
                float4 va = arow[kf];
                uint4 ta = make_uint4(tf32_of(va.x * um), tf32_of(va.y * um),
                                      tf32_of(va.z * um), tf32_of(va.w * um));
                *(uint4*)&As[m * KPAD + kf * 4] = ta;
                float4 vb = brow[kf];
                uint4 tb = make_uint4(tf32_of(vb.x * im), tf32_of(vb.y * im),
                                      tf32_of(vb.z * im), tf32_of(vb.w * im));
                *(uint4*)&Bs[m * KPAD + kf * 4] = tb;
            }
        }
    }
    __syncthreads();

    const int lane = t & 31, warp = t >> 5;
    const int wm = warp >> 2;          // 0..1  -> 64 rows
    const int wn = warp & 3;           // 0..3  -> 32 cols
    const int lr = lane >> 2;          // 0..7
    const int lc = lane & 3;           // 0..3

    // ldmatrix per-lane source rows.
    const int amat = lane >> 3, ar = lane & 7;
    const int aRow = wm * 64 + (amat & 1) * 8 + ar;
    const int aKo  = (amat >> 1) * 4;
    const int bmat = (lane >> 3) & 1, br = lane & 7;
    const int bRow = wn * 32 + br;
    const int bKo  = bmat * 4;

    const uint32_t As_s = (uint32_t)__cvta_generic_to_shared(As);
    const uint32_t Bs_s = (uint32_t)__cvta_generic_to_shared(Bs);

    float acc[4][4][4];
#pragma unroll
    for (int ma = 0; ma < 4; ++ma)
#pragma unroll
        for (int na = 0; na < 4; ++na)
#pragma unroll
            for (int j = 0; j < 4; ++j) acc[ma][na][j] = 0.f;

#pragma unroll
    for (int ks = 0; ks < 8; ++ks) {
        uint32_t a[4][4], b[4][2];
#pragma unroll
        for (int ma = 0; ma < 4; ++ma)
            ldsm_x4(a[ma], As_s + (uint32_t)(((aRow + ma * 16) * KPAD) + ks * 8 + aKo) * 4u);
#pragma unroll
        for (int na = 0; na < 4; ++na)
            ldsm_x2(b[na], Bs_s + (uint32_t)(((bRow + na * 8) * KPAD) + ks * 8 + bKo) * 4u);
#pragma unroll
        for (int ma = 0; ma < 4; ++ma)
#pragma unroll
            for (int na = 0; na < 4; ++na)
                mma_tf32(acc[ma][na], a[ma], b[na]);
    }

    // Writeback pred tile with streaming stores.
#pragma unroll
    for (int ma = 0; ma < 4; ++ma) {
        const int r = wm * 64 + ma * 16 + lr;
#pragma unroll
        for (int na = 0; na < 4; ++na) {
            const int c = wn * 32 + na * 8 + 2 * lc;
            __stcs((float2*)(pred + (size_t)r * NUM_ITEM + c),
                   make_float2(acc[ma][na][0], acc[ma][na][1]));
            __stcs((float2*)(pred + (size_t)(r + 8) * NUM_ITEM + c),
                   make_float2(acc[ma][na][2], acc[ma][na][3]));
        }
    }
}

// ---------------------------------------------------------------------------
// Kernel 4: scatter-add ratings into label (duplicates accumulate).
// ---------------------------------------------------------------------------
__global__ void scatter_label(const void* __restrict__ idxv,
                              const float* __restrict__ ratings,
                              float* __restrict__ out) {
    int t = blockIdx.x * blockDim.x + threadIdx.x;
    float* label = out + (size_t)NUM_USER * NUM_ITEM;
#pragma unroll
    for (int rep = 0; rep < 2; ++rep) {
        int e = t * 2 + rep;
        if (e < NNZ) {
            int u, i;
            load_pair(idxv, e, u, i);
            atomicAdd(label + (size_t)u * NUM_ITEM + i, __ldg(ratings + e));
        }
    }
}

extern "C" void kernel_launch(void* const* d_in, const int* in_sizes, int n_in,
                              void* d_out, int out_size) {
    const float* eu      = (const float*)d_in[0];
    const float* ei      = (const float*)d_in[1];
    const void*  idx     = d_in[2];
    const float* ratings = (const float*)d_in[3];
    float* out = (float*)d_out;

    clear_masks<<<16, 256>>>((const int*)idx, out);
    set_masks<<<(NNZ + 255) / 256, 256>>>(idx);
    fill_label<<<4864, 256>>>(out);
    dim3 grid(NUM_ITEM / BN, NUM_USER / BM);
    mf_gemm<<<grid, 256>>>(eu, ei, out);
    scatter_label<<<(NNZ / 2 + 255) / 256, 256>>>(idx, ratings, out);
}

// round 16
// speedup vs baseline: 1.6106x; 1.6106x over previous
#include <cuda_runtime.h>
#include <cuda_bf16.h>
#include <cstdint>

#define NUM_USER  8192
#define NUM_ITEM  16384
#define NUM_HIDDEN 64
#define NNZ       200000

#define BM 128
#define BN 128
#define KPAD 68   // smem row stride in words: all ldmatrix phases conflict-free

__device__ unsigned char g_user_mask[NUM_USER];
__device__ unsigned char g_item_mask[NUM_ITEM];
__device__ unsigned char g_user_tile[NUM_USER / BM];   // 64 tile-row flags
__device__ unsigned char g_item_tile[NUM_ITEM / BN];   // 128 tile-col flags
__device__ int g_idx_is64;

// ---------------------------------------------------------------------------
// mma / ldmatrix / cp.async helpers
// ---------------------------------------------------------------------------
__device__ __forceinline__ void mma_tf32(float* c, const uint32_t* a, const uint32_t* b) {
    asm("mma.sync.aligned.m16n8k8.row.col.f32.tf32.tf32.f32 "
        "{%0,%1,%2,%3}, {%4,%5,%6,%7}, {%8,%9}, {%0,%1,%2,%3};"
        : "+f"(c[0]), "+f"(c[1]), "+f"(c[2]), "+f"(c[3])
        : "r"(a[0]), "r"(a[1]), "r"(a[2]), "r"(a[3]), "r"(b[0]), "r"(b[1]));
}

__device__ __forceinline__ void ldsm_x4(uint32_t* r, uint32_t saddr) {
    asm volatile("ldmatrix.sync.aligned.m8n8.x4.shared.b16 {%0,%1,%2,%3}, [%4];"
        : "=r"(r[0]), "=r"(r[1]), "=r"(r[2]), "=r"(r[3]) : "r"(saddr));
}

__device__ __forceinline__ void ldsm_x2(uint32_t* r, uint32_t saddr) {
    asm volatile("ldmatrix.sync.aligned.m8n8.x2.shared.b16 {%0,%1}, [%2];"
        : "=r"(r[0]), "=r"(r[1]) : "r"(saddr));
}

__device__ __forceinline__ void cp_async16(uint32_t saddr, const void* gaddr) {
    asm volatile("cp.async.cg.shared.global [%0], [%1], 16;"
        :: "r"(saddr), "l"(gaddr));
}

__device__ __forceinline__ void cp_async_wait_all() {
    asm volatile("cp.async.commit_group;\n\tcp.async.wait_group 0;" ::: "memory");
}

// ---------------------------------------------------------------------------
// Kernel 1: clear masks + tile flags, detect index dtype, write ratio.
// ---------------------------------------------------------------------------
__global__ void clear_masks(const int* __restrict__ idx32, float* __restrict__ out) {
    int t = blockIdx.x * blockDim.x + threadIdx.x;
    if (t == 0) {
        int all0 = 1;
#pragma unroll
        for (int k = 0; k < 64; ++k) all0 &= (idx32[2 * k + 1] == 0);
        g_idx_is64 = all0;
        out[(size_t)2 * NUM_USER * NUM_ITEM] =
            (float)((double)NUM_USER * (double)NUM_ITEM / (double)NNZ);
    }
    int* um = (int*)g_user_mask;
    int* im = (int*)g_item_mask;
    if (t < NUM_USER / 4) um[t] = 0;
    if (t < NUM_ITEM / 4) im[t] = 0;
    if (t < NUM_USER / BM) g_user_tile[t] = 0;
    if (t < NUM_ITEM / BN) g_item_tile[t] = 0;
}

__device__ __forceinline__ void load_pair(const void* idxv, int t, int& u, int& i) {
    if (g_idx_is64) {
        const long long* p = (const long long*)idxv;
        u = (int)__ldg(p + t);
        i = (int)__ldg(p + NNZ + t);
    } else {
        const int* p = (const int*)idxv;
        u = __ldg(p + t);
        i = __ldg(p + NNZ + t);
    }
}

__global__ void set_masks(const void* __restrict__ idxv) {
    int t = blockIdx.x * blockDim.x + threadIdx.x;
    if (t >= NNZ) return;
    int u, i;
    load_pair(idxv, t, u, i);
    g_user_mask[u] = 1;
    g_item_mask[i] = 1;
    g_user_tile[u >> 7] = 1;
    g_item_tile[i >> 7] = 1;
}

// ---------------------------------------------------------------------------
// Zero a 128x128 tile: contiguous 512B warp bursts, streaming stores.
// ---------------------------------------------------------------------------
__device__ __forceinline__ void zero_tile(float* base, int t) {
    const float4 z = make_float4(0.f, 0.f, 0.f, 0.f);
    const int warp = t >> 5, lane = t & 31;
#pragma unroll
    for (int r = warp; r < BM; r += 8)
        __stcs((float4*)(base + (size_t)r * NUM_ITEM) + lane, z);
}

// ---------------------------------------------------------------------------
// Kernel 3: fused masked tf32-MMA GEMM + label-tile zeroing.
// Tile liveness via precomputed flags (no barrier), cp.async raw staging
// (mma consumes fp32 bits as tf32 = truncation), masks applied in epilogue.
// One __syncthreads per live block.
// ---------------------------------------------------------------------------
__global__ void __launch_bounds__(256, 2)
mf_gemm(const float* __restrict__ eu, const float* __restrict__ ei,
        float* __restrict__ out) {
    __shared__ uint32_t As[BM * KPAD];
    __shared__ uint32_t Bs[BN * KPAD];

    const int t    = threadIdx.x;
    const int row0 = blockIdx.y * BM;
    const int col0 = blockIdx.x * BN;

    float* pred  = out + (size_t)row0 * NUM_ITEM + col0;
    float* label = pred + (size_t)NUM_USER * NUM_ITEM;

    // Uniform tile-liveness check: two broadcast byte loads, no barrier.
    if (!(g_user_tile[blockIdx.y] && g_item_tile[blockIdx.x])) {
        zero_tile(pred, t);
        zero_tile(label, t);
        return;
    }

    // Fire-and-forget label zeroing: drains while we stage/compute.
    zero_tile(label, t);

    // Stage A and B raw (fp32 bits) via cp.async — no RF round-trip, no cvt.
    {
        const int rsub = t >> 2;   // 0..63
        const int f4   = t & 3;
        const uint32_t As_b = (uint32_t)__cvta_generic_to_shared(As);
        const uint32_t Bs_b = (uint32_t)__cvta_generic_to_shared(Bs);
#pragma unroll
        for (int pass = 0; pass < 2; ++pass) {
            const int m = rsub + 64 * pass;
            const char* arow = (const char*)(eu + (size_t)(row0 + m) * NUM_HIDDEN);
            const char* brow = (const char*)(ei + (size_t)(col0 + m) * NUM_HIDDEN);
#pragma unroll
            for (int q = 0; q < 4; ++q) {
                const int kf = f4 + 4 * q;          // 16B chunk 0..15
                cp_async16(As_b + (uint32_t)(m * KPAD + kf * 4) * 4u, arow + kf * 16);
                cp_async16(Bs_b + (uint32_t)(m * KPAD + kf * 4) * 4u, brow + kf * 16);
            }
        }
    }
    cp_async_wait_all();
    __syncthreads();

    const int lane = t & 31, warp = t >> 5;
    const int wm = warp >> 2;          // 0..1  -> 64 rows
    const int wn = warp & 3;           // 0..3  -> 32 cols
    const int lr = lane >> 2;          // 0..7
    const int lc = lane & 3;           // 0..3

    // ldmatrix per-lane source rows.
    const int amat = lane >> 3, ar = lane & 7;
    const int aRow = wm * 64 + (amat & 1) * 8 + ar;
    const int aKo  = (amat >> 1) * 4;
    const int bmat = (lane >> 3) & 1, br = lane & 7;
    const int bRow = wn * 32 + br;
    const int bKo  = bmat * 4;

    const uint32_t As_s = (uint32_t)__cvta_generic_to_shared(As);
    const uint32_t Bs_s = (uint32_t)__cvta_generic_to_shared(Bs);

    float acc[4][4][4];
#pragma unroll
    for (int ma = 0; ma < 4; ++ma)
#pragma unroll
        for (int na = 0; na < 4; ++na)
#pragma unroll
            for (int j = 0; j < 4; ++j) acc[ma][na][j] = 0.f;

#pragma unroll
    for (int ks = 0; ks < 8; ++ks) {
        uint32_t a[4][4], b[4][2];
#pragma unroll
        for (int ma = 0; ma < 4; ++ma)
            ldsm_x4(a[ma], As_s + (uint32_t)(((aRow + ma * 16) * KPAD) + ks * 8 + aKo) * 4u);
#pragma unroll
        for (int na = 0; na < 4; ++na)
            ldsm_x2(b[na], Bs_s + (uint32_t)(((bRow + na * 8) * KPAD) + ks * 8 + bKo) * 4u);
#pragma unroll
        for (int ma = 0; ma < 4; ++ma)
#pragma unroll
            for (int na = 0; na < 4; ++na)
                mma_tf32(acc[ma][na], a[ma], b[na]);
    }

    // Epilogue: apply row/col masks (0/1) and store with streaming stores.
    float umv[4][2], imv[4][2];
#pragma unroll
    for (int ma = 0; ma < 4; ++ma) {
        const int r = row0 + wm * 64 + ma * 16 + lr;
        umv[ma][0] = (float)g_user_mask[r];
        umv[ma][1] = (float)g_user_mask[r + 8];
    }
#pragma unroll
    for (int na = 0; na < 4; ++na) {
        const int c = col0 + wn * 32 + na * 8 + 2 * lc;
        imv[na][0] = (float)g_item_mask[c];
        imv[na][1] = (float)g_item_mask[c + 1];
    }

#pragma unroll
    for (int ma = 0; ma < 4; ++ma) {
        const int r = wm * 64 + ma * 16 + lr;
#pragma unroll
        for (int na = 0; na < 4; ++na) {
            const int c = wn * 32 + na * 8 + 2 * lc;
            __stcs((float2*)(pred + (size_t)r * NUM_ITEM + c),
                   make_float2(acc[ma][na][0] * umv[ma][0] * imv[na][0],
                               acc[ma][na][1] * umv[ma][0] * imv[na][1]));
            __stcs((float2*)(pred + (size_t)(r + 8) * NUM_ITEM + c),
                   make_float2(acc[ma][na][2] * umv[ma][1] * imv[na][0],
                               acc[ma][na][3] * umv[ma][1] * imv[na][1]));
        }
    }
}

// ---------------------------------------------------------------------------
// Kernel 4: scatter-add ratings into label (duplicates accumulate).
// ---------------------------------------------------------------------------
__global__ void scatter_label(const void* __restrict__ idxv,
                              const float* __restrict__ ratings,
                              float* __restrict__ out) {
    int t = blockIdx.x * blockDim.x + threadIdx.x;
    float* label = out + (size_t)NUM_USER * NUM_ITEM;
#pragma unroll
    for (int rep = 0; rep < 2; ++rep) {
        int e = t * 2 + rep;
        if (e < NNZ) {
            int u, i;
            load_pair(idxv, e, u, i);
            atomicAdd(label + (size_t)u * NUM_ITEM + i, __ldg(ratings + e));
        }
    }
}

extern "C" void kernel_launch(void* const* d_in, const int* in_sizes, int n_in,
                              void* d_out, int out_size) {
    const float* eu      = (const float*)d_in[0];
    const float* ei      = (const float*)d_in[1];
    const void*  idx     = d_in[2];
    const float* ratings = (const float*)d_in[3];
    float* out = (float*)d_out;

    clear_masks<<<16, 256>>>((const int*)idx, out);
    set_masks<<<(NNZ + 255) / 256, 256>>>(idx);
    dim3 grid(NUM_ITEM / BN, NUM_USER / BM);
    mf_gemm<<<grid, 256>>>(eu, ei, out);
    scatter_label<<<(NNZ / 2 + 255) / 256, 256>>>(idx, ratings, out);
}